// round 12
// baseline (speedup 1.0000x reference)
#include <cuda_runtime.h>
#include <cuda_fp16.h>
#include <cstdint>

#define BSZ   128
#define NIN   784
#define NHID  1024
#define NOUT  10
#define TT    200
#define NPAIR (TT * BSZ)          // 25600
#define ALPHA 0.05f
#define KPAD  832                  // 13 * 64 (K padded with zeros)
#define NCH   13                   // K chunks of 64

// -------------------- scratch (static device globals) ---------------------
__device__ unsigned short g_A[(size_t)NPAIR * KPAD];   // fp16 spikes  (pair, k)
__device__ unsigned short g_B[(size_t)NHID * KPAD];    // fp16 relu(w1)^T (n, k)
__device__ unsigned short g_Ih[(size_t)NPAIR * NHID];  // fp16 I_h (pair, h)
__device__ float          g_part[(size_t)BSZ * TT * NOUT]; // neg sums (b,t,o)
__device__ float          g_colsum[NOUT];              // sum_h relu(w2[h][o])

// --------------------------------------------------------------------------
// kA: stage spikes as fp16 A[(t*B+b), i], K padded to 832. 64-input blocks;
// half2 stores -> full 128B lines per warp.
// --------------------------------------------------------------------------
__global__ void __launch_bounds__(256) kA_stage(const float* __restrict__ sp) {
    extern __shared__ float tile[];   // [64][201]
    const int b = blockIdx.x;
    const int i0 = blockIdx.y * 64;
    for (int l = threadIdx.x; l < 64 * 200; l += 256) {
        int ii = l / 200, t = l - ii * 200;
        int i = i0 + ii;
        float v = (i < NIN) ? sp[((size_t)b * NIN + i) * TT + t] : 0.0f;
        tile[ii * 201 + t] = v;
    }
    __syncthreads();
    __half2* A2 = (__half2*)g_A;
    for (int l = threadIdx.x; l < 32 * 200; l += 256) {
        int t = l >> 5, iq = l & 31;
        __half2 v = __floats2half2_rn(tile[(iq * 2) * 201 + t],
                                      tile[(iq * 2 + 1) * 201 + t]);
        A2[(((size_t)t * BSZ + b) * KPAD + i0) / 2 + iq] = v;
    }
}

// --------------------------------------------------------------------------
// kB: stage relu(w1)^T as fp16 B[n, i]. Blocks with y==26 zero g_part;
// (x==0, y==26) additionally reduces colsum(relu(w2)) into g_colsum.
// --------------------------------------------------------------------------
__global__ void __launch_bounds__(256) kB_stage(const float* __restrict__ w1,
                                                const float* __restrict__ w2) {
    if (blockIdx.y == 26) {
        const int base = (blockIdx.x * 256 + threadIdx.x) * 4;
        for (int idx = base; idx < BSZ * TT * NOUT; idx += 32 * 256 * 4)
            *reinterpret_cast<float4*>(g_part + idx) = make_float4(0.f, 0.f, 0.f, 0.f);
        if (blockIdx.x == 0) {
            __shared__ float cs[NOUT];
            const int tid = threadIdx.x;
            if (tid < NOUT) cs[tid] = 0.0f;
            __syncthreads();
            float part[NOUT];
            #pragma unroll
            for (int o = 0; o < NOUT; o++) part[o] = 0.0f;
            for (int h = tid; h < NHID; h += 256) {
                #pragma unroll
                for (int o = 0; o < NOUT; o++)
                    part[o] += fmaxf(w2[(size_t)h * NOUT + o], 0.0f);
            }
            #pragma unroll
            for (int o = 0; o < NOUT; o++) atomicAdd(cs + o, part[o]);
            __syncthreads();
            if (tid < NOUT) g_colsum[tid] = cs[tid];
        }
        return;
    }
    __shared__ float tile[32][33];
    const int n0 = blockIdx.x * 32;
    const int i0 = blockIdx.y * 32;
    const int r = threadIdx.x >> 5, c = threadIdx.x & 31;
    for (int rr = r; rr < 32; rr += 8) {
        int i = i0 + rr;
        tile[rr][c] = (i < NIN) ? fmaxf(w1[(size_t)i * NHID + n0 + c], 0.0f) : 0.0f;
    }
    __syncthreads();
    __half* B = (__half*)g_B;
    for (int cc = r; cc < 32; cc += 8)
        B[((size_t)(n0 + cc)) * KPAD + i0 + c] = __float2half(tile[c][cc]);
}

// --------------------------------------------------------------------------
// common PTX helpers
// --------------------------------------------------------------------------
__device__ __forceinline__ uint32_t smem_u32(const void* p) {
    uint32_t a;
    asm("{ .reg .u64 t; cvta.to.shared.u64 t, %1; cvt.u32.u64 %0, t; }"
        : "=r"(a) : "l"(p));
    return a;
}
__device__ __forceinline__ void mma16816h(uint32_t* c, uint32_t a0, uint32_t a1,
                                          uint32_t a2, uint32_t a3,
                                          uint32_t b0, uint32_t b1) {
    asm volatile(
        "mma.sync.aligned.m16n8k16.row.col.f16.f16.f16.f16 "
        "{%0,%1}, {%2,%3,%4,%5}, {%6,%7}, {%0,%1};"
        : "+r"(c[0]), "+r"(c[1])
        : "r"(a0), "r"(a1), "r"(a2), "r"(a3), "r"(b0), "r"(b1));
}
__device__ __forceinline__ void ldsm4(uint32_t& r0, uint32_t& r1,
                                      uint32_t& r2, uint32_t& r3, uint32_t addr) {
    asm volatile("ldmatrix.sync.aligned.m8n8.x4.shared.b16 {%0,%1,%2,%3}, [%4];"
                 : "=r"(r0), "=r"(r1), "=r"(r2), "=r"(r3) : "r"(addr));
}
__device__ __forceinline__ void cp16(uint32_t saddr, const void* gptr) {
    asm volatile("cp.async.cg.shared.global [%0], [%1], 16;"
                 :: "r"(saddr), "l"(gptr));
}
#define CP_COMMIT() asm volatile("cp.async.commit_group;" ::: "memory")
#define CP_WAIT(n)  asm volatile("cp.async.wait_group %0;" :: "n"(n) : "memory")

#define STAGE_BYTES 32768

// --------------------------------------------------------------------------
// k_gemm: I_h = A @ B^T, f16 HMMA with f16 accumulation, cp.async 3-stage.
// CTA 128x128, 4 warps, warp tile 64x64. XOR-swizzled SMEM + ldmatrix.
// --------------------------------------------------------------------------
__global__ void __launch_bounds__(128, 2) k_gemm() {
    __shared__ __align__(16) uint8_t smbuf[3 * STAGE_BYTES];

    const int tid  = threadIdx.x;
    const int warp = tid >> 5, lane = tid & 31;
    const int wm = warp & 1;
    const int wn = warp >> 1;
    const int n0 = blockIdx.x * 128;
    const int p0 = blockIdx.y * 128;
    const __half* A  = (const __half*)g_A;
    const __half* Bm = (const __half*)g_B;
    const uint32_t sbase = smem_u32(smbuf);

    const int srow = tid >> 3;
    const int sc   = tid & 7;

    uint32_t acc[4][8][2];
    #pragma unroll
    for (int mt = 0; mt < 4; mt++)
        #pragma unroll
        for (int nt = 0; nt < 8; nt++) { acc[mt][nt][0] = 0u; acc[mt][nt][1] = 0u; }

    auto issue = [&](int c, int s) {
        const uint32_t st0 = sbase + s * STAGE_BYTES;
        const size_t kof = (size_t)c * 64 + sc * 8;
        #pragma unroll
        for (int it = 0; it < 8; it++) {
            const int row = it * 16 + srow;
            const int off = row * 128 + ((sc ^ (row & 7)) << 4);
            cp16(st0 + off,         A  + (size_t)(p0 + row) * KPAD + kof);
            cp16(st0 + 16384 + off, Bm + (size_t)(n0 + row) * KPAD + kof);
        }
        CP_COMMIT();
    };

    issue(0, 0);
    issue(1, 1);

    #pragma unroll 1
    for (int c = 0; c < NCH; c++) {
        if (c + 2 < NCH) { CP_WAIT(1); } else { CP_WAIT(0); }
        __syncthreads();
        if (c + 2 < NCH) issue(c + 2, (c + 2) % 3);

        const uint32_t sa = sbase + (c % 3) * STAGE_BYTES;
        const uint32_t sb = sa + 16384;

        #pragma unroll
        for (int ks = 0; ks < 4; ks++) {
            const int kch = ks * 2 + (lane >> 4);
            uint32_t af[4][4];
            #pragma unroll
            for (int mt = 0; mt < 4; mt++) {
                const int r = wm * 64 + mt * 16 + (lane & 15);
                ldsm4(af[mt][0], af[mt][1], af[mt][2], af[mt][3],
                      sa + r * 128 + ((kch ^ (r & 7)) << 4));
            }
            #pragma unroll
            for (int nt2 = 0; nt2 < 4; nt2++) {
                const int r = wn * 64 + nt2 * 16 + (lane & 15);
                uint32_t b0, b1, b2, b3;
                ldsm4(b0, b1, b2, b3, sb + r * 128 + ((kch ^ (r & 7)) << 4));
                #pragma unroll
                for (int mt = 0; mt < 4; mt++) {
                    mma16816h(acc[mt][2 * nt2],     af[mt][0], af[mt][1], af[mt][2], af[mt][3], b0, b2);
                    mma16816h(acc[mt][2 * nt2 + 1], af[mt][0], af[mt][1], af[mt][2], af[mt][3], b1, b3);
                }
            }
        }
        __syncthreads();
    }

    __half* Ih = (__half*)g_Ih;
    #pragma unroll
    for (int mt = 0; mt < 4; mt++) {
        const int m = p0 + wm * 64 + mt * 16 + (lane >> 2);
        #pragma unroll
        for (int nt = 0; nt < 8; nt++) {
            const int n = n0 + wn * 64 + nt * 8 + (lane & 3) * 2;
            *reinterpret_cast<uint32_t*>(Ih + (size_t)m * NHID + n)       = acc[mt][nt][0];
            *reinterpret_cast<uint32_t*>(Ih + (size_t)(m + 8) * NHID + n) = acc[mt][nt][1];
        }
    }
}

// --------------------------------------------------------------------------
// k3: hidden LIF + fused output-layer neg contributions.
// cp.async double-buffered I staging (proven in R11).
// --------------------------------------------------------------------------
#define LCHUNK 40
#define LSTAGE (LCHUNK * 256 * 2)   // 20480 bytes

__global__ void __launch_bounds__(256) k_lif_hidden(const float* __restrict__ w2,
                                                    float* __restrict__ hs_out) {
    __shared__ __align__(16) uint8_t sbuf[2 * LSTAGE];
    const int tid = threadIdx.x;
    const int bh = blockIdx.x * 256 + tid;
    const int b = bh >> 10;
    const int h = bh & 1023;
    const int h0 = (blockIdx.x & 3) * 256;
    const uint32_t sb = smem_u32(sbuf);
    const __half* Ihg = (const __half*)g_Ih;
    float* obase = hs_out + (size_t)bh * TT;

    const int t8 = tid >> 5;
    const int sl = tid & 31;

    auto issue = [&](int chunk, int buf) {
        const uint32_t st0 = sb + buf * LSTAGE;
        #pragma unroll
        for (int q = 0; q < 5; q++) {
            const int t = t8 + 8 * q;
            const __half* src = Ihg + (size_t)(chunk * LCHUNK + t) * (BSZ * NHID)
                                + (size_t)b * NHID + h0 + sl * 8;
            cp16(st0 + t * 512 + sl * 16, src);
        }
        CP_COMMIT();
    };

    issue(0, 0);

    float v = 0.0f;
    #pragma unroll 1
    for (int c = 0; c < TT / LCHUNK; c++) {
        if (c + 1 < TT / LCHUNK) issue(c + 1, (c + 1) & 1);
        if (c + 1 < TT / LCHUNK) { CP_WAIT(1); } else { CP_WAIT(0); }
        __syncthreads();

        const __half* ssrc = (const __half*)(sbuf + (c & 1) * LSTAGE);
        const int tc = c * LCHUNK;
        float rr[LCHUNK];
        #pragma unroll
        for (int j = 0; j < LCHUNK; j++) {
            float I = __half2float(ssrc[j * 256 + tid]);
            v = __fadd_rn(__fadd_rn(v, __fmul_rn(ALPHA, -v)), I);
            float s;
            if (v >= 1.0f) { s = 1.0f; v = 0.0f; }
            else {
                s = 0.0f;
                float* pb = g_part + ((size_t)b * TT + (tc + j)) * NOUT;
                #pragma unroll
                for (int o = 0; o < NOUT; o++)
                    atomicAdd(pb + o, fmaxf(w2[(size_t)h * NOUT + o], 0.0f));
            }
            rr[j] = s;
        }
        #pragma unroll
        for (int q = 0; q < LCHUNK / 4; q++) {
            float4 o4 = make_float4(rr[4*q], rr[4*q+1], rr[4*q+2], rr[4*q+3]);
            *reinterpret_cast<float4*>(obase + tc + 4*q) = o4;
        }
        __syncthreads();
    }
}

// --------------------------------------------------------------------------
// k4b: output LIF + firing rates. thread per (b,o). colsum precomputed;
// t-loop processed in 10-wide chunks with batched independent neg loads.
// --------------------------------------------------------------------------
__global__ void k_out_lif(float* __restrict__ os_out,
                          float* __restrict__ fr_out) {
    const int gid = blockIdx.x * blockDim.x + threadIdx.x;
    if (gid >= BSZ * NOUT) return;
    const int b = gid / NOUT;
    const int o = gid - b * NOUT;

    const float colsum = g_colsum[o];
    const float* pb = g_part + (size_t)b * TT * NOUT + o;
    float v = 0.0f, cnt = 0.0f;
    float* ob = os_out + ((size_t)b * NOUT + o) * TT;

    #pragma unroll 1
    for (int tc = 0; tc < TT; tc += 10) {
        float neg[10];
        #pragma unroll
        for (int j = 0; j < 10; j++) {
            const int t = tc + j;
            neg[j] = (t > 0) ? pb[(size_t)(t - 1) * NOUT] : 0.0f;
        }
        float out[10];
        #pragma unroll
        for (int j = 0; j < 10; j++) {
            const int t = tc + j;
            float I = (t > 0) ? (colsum - neg[j]) : 0.0f;
            v = __fadd_rn(__fadd_rn(v, __fmul_rn(ALPHA, -v)), I);
            float s = (v >= 1.0f) ? 1.0f : 0.0f;
            if (v >= 1.0f) v = 0.0f;
            out[j] = s;
            cnt += s;
        }
        #pragma unroll
        for (int j = 0; j < 10; j++) ob[tc + j] = out[j];
    }
    fr_out[gid] = cnt / (float)TT;
}

// --------------------------------------------------------------------------
extern "C" void kernel_launch(void* const* d_in, const int* in_sizes, int n_in,
                              void* d_out, int out_size) {
    const float* sp = (const float*)d_in[0];   // (128, 784, 200)
    const float* w1 = (const float*)d_in[1];   // (784, 1024)
    const float* w2 = (const float*)d_in[2];   // (1024, 10)

    float* hs = (float*)d_out;                          // (B, NHID, T)
    float* os = hs + (size_t)BSZ * NHID * TT;           // (B, NOUT, T)
    float* fr = os + (size_t)BSZ * NOUT * TT;           // (B, NOUT)

    cudaFuncSetAttribute(kA_stage, cudaFuncAttributeMaxDynamicSharedMemorySize,
                         64 * 201 * (int)sizeof(float));

    kA_stage<<<dim3(BSZ, 13), 256, 64 * 201 * sizeof(float)>>>(sp);
    kB_stage<<<dim3(32, 27), 256>>>(w1, w2);
    k_gemm<<<dim3(NHID / 128, NPAIR / 128), 128>>>();
    k_lif_hidden<<<(BSZ * NHID) / 256, 256>>>(w2, hs);
    k_out_lif<<<5, 256>>>(os, fr);
}

// round 13
// speedup vs baseline: 1.0708x; 1.0708x over previous
#include <cuda_runtime.h>
#include <cuda_fp16.h>
#include <cstdint>

#define BSZ   128
#define NIN   784
#define NHID  1024
#define NOUT  10
#define TT    200
#define NPAIR (TT * BSZ)          // 25600
#define ALPHA 0.05f
#define KPAD  832                  // 13 * 64 (K padded with zeros)
#define NCH   13                   // K chunks of 64

// -------------------- scratch (static device globals) ---------------------
__device__ unsigned short g_A[(size_t)NPAIR * KPAD];   // fp16 spikes  (pair, k)
__device__ unsigned short g_B[(size_t)NHID * KPAD];    // fp16 relu(w1)^T (n, k)
__device__ unsigned short g_Ih[(size_t)NPAIR * NHID];  // fp16 I_h (pair, h)
__device__ float          g_part[(size_t)BSZ * TT * NOUT]; // neg sums (b,t,o)
__device__ float          g_colsum[NOUT];              // sum_h relu(w2[h][o])

// --------------------------------------------------------------------------
// kA: stage spikes as fp16 A[(t*B+b), i] (R11 version — 32-input tiles).
// --------------------------------------------------------------------------
__global__ void __launch_bounds__(256) kA_stage(const float* __restrict__ sp) {
    extern __shared__ float tile[];   // [32][201]
    const int b = blockIdx.x;
    const int i0 = blockIdx.y * 32;
    for (int l = threadIdx.x; l < 32 * 200; l += 256) {
        int ii = l / 200, t = l - ii * 200;
        int i = i0 + ii;
        float v = (i < NIN) ? sp[((size_t)b * NIN + i) * TT + t] : 0.0f;
        tile[ii * 201 + t] = v;
    }
    __syncthreads();
    __half* A = (__half*)g_A;
    for (int l = threadIdx.x; l < 32 * 200; l += 256) {
        int t = l >> 5, ii = l & 31;
        A[((size_t)t * BSZ + b) * KPAD + i0 + ii] = __float2half(tile[ii * 201 + t]);
    }
}

// --------------------------------------------------------------------------
// kB: stage relu(w1)^T as fp16 B[n, i]. y==26 blocks zero g_part; (0,26)
// also reduces colsum(relu(w2)) into g_colsum.
// --------------------------------------------------------------------------
__global__ void __launch_bounds__(256) kB_stage(const float* __restrict__ w1,
                                                const float* __restrict__ w2) {
    if (blockIdx.y == 26) {
        const int base = (blockIdx.x * 256 + threadIdx.x) * 4;
        for (int idx = base; idx < BSZ * TT * NOUT; idx += 32 * 256 * 4)
            *reinterpret_cast<float4*>(g_part + idx) = make_float4(0.f, 0.f, 0.f, 0.f);
        if (blockIdx.x == 0) {
            __shared__ float cs[NOUT];
            const int tid = threadIdx.x;
            if (tid < NOUT) cs[tid] = 0.0f;
            __syncthreads();
            float part[NOUT];
            #pragma unroll
            for (int o = 0; o < NOUT; o++) part[o] = 0.0f;
            for (int h = tid; h < NHID; h += 256) {
                #pragma unroll
                for (int o = 0; o < NOUT; o++)
                    part[o] += fmaxf(w2[(size_t)h * NOUT + o], 0.0f);
            }
            #pragma unroll
            for (int o = 0; o < NOUT; o++) atomicAdd(cs + o, part[o]);
            __syncthreads();
            if (tid < NOUT) g_colsum[tid] = cs[tid];
        }
        return;
    }
    __shared__ float tile[32][33];
    const int n0 = blockIdx.x * 32;
    const int i0 = blockIdx.y * 32;
    const int r = threadIdx.x >> 5, c = threadIdx.x & 31;
    for (int rr = r; rr < 32; rr += 8) {
        int i = i0 + rr;
        tile[rr][c] = (i < NIN) ? fmaxf(w1[(size_t)i * NHID + n0 + c], 0.0f) : 0.0f;
    }
    __syncthreads();
    __half* B = (__half*)g_B;
    for (int cc = r; cc < 32; cc += 8)
        B[((size_t)(n0 + cc)) * KPAD + i0 + c] = __float2half(tile[c][cc]);
}

// --------------------------------------------------------------------------
// common PTX helpers
// --------------------------------------------------------------------------
__device__ __forceinline__ uint32_t smem_u32(const void* p) {
    uint32_t a;
    asm("{ .reg .u64 t; cvta.to.shared.u64 t, %1; cvt.u32.u64 %0, t; }"
        : "=r"(a) : "l"(p));
    return a;
}
__device__ __forceinline__ void mma16816h(uint32_t* c, uint32_t a0, uint32_t a1,
                                          uint32_t a2, uint32_t a3,
                                          uint32_t b0, uint32_t b1) {
    asm volatile(
        "mma.sync.aligned.m16n8k16.row.col.f16.f16.f16.f16 "
        "{%0,%1}, {%2,%3,%4,%5}, {%6,%7}, {%0,%1};"
        : "+r"(c[0]), "+r"(c[1])
        : "r"(a0), "r"(a1), "r"(a2), "r"(a3), "r"(b0), "r"(b1));
}
__device__ __forceinline__ void ldsm4(uint32_t& r0, uint32_t& r1,
                                      uint32_t& r2, uint32_t& r3, uint32_t addr) {
    asm volatile("ldmatrix.sync.aligned.m8n8.x4.shared.b16 {%0,%1,%2,%3}, [%4];"
                 : "=r"(r0), "=r"(r1), "=r"(r2), "=r"(r3) : "r"(addr));
}
__device__ __forceinline__ void cp16(uint32_t saddr, const void* gptr) {
    asm volatile("cp.async.cg.shared.global [%0], [%1], 16;"
                 :: "r"(saddr), "l"(gptr));
}
#define CP_COMMIT() asm volatile("cp.async.commit_group;" ::: "memory")
#define CP_WAIT(n)  asm volatile("cp.async.wait_group %0;" :: "n"(n) : "memory")

#define STAGE_BYTES 32768

// --------------------------------------------------------------------------
// k_gemm: I_h = A @ B^T, f16 HMMA f16-acc. 2-stage cp.async pipeline,
// 64KB SMEM/CTA -> 3 CTAs/SM = 12 warps/SM. CTA 128x128, warp tile 64x64.
// --------------------------------------------------------------------------
__global__ void __launch_bounds__(128, 3) k_gemm() {
    __shared__ __align__(16) uint8_t smbuf[2 * STAGE_BYTES];

    const int tid  = threadIdx.x;
    const int warp = tid >> 5, lane = tid & 31;
    const int wm = warp & 1;
    const int wn = warp >> 1;
    const int n0 = blockIdx.x * 128;
    const int p0 = blockIdx.y * 128;
    const __half* A  = (const __half*)g_A;
    const __half* Bm = (const __half*)g_B;
    const uint32_t sbase = smem_u32(smbuf);

    const int srow = tid >> 3;
    const int sc   = tid & 7;

    uint32_t acc[4][8][2];
    #pragma unroll
    for (int mt = 0; mt < 4; mt++)
        #pragma unroll
        for (int nt = 0; nt < 8; nt++) { acc[mt][nt][0] = 0u; acc[mt][nt][1] = 0u; }

    auto issue = [&](int c, int s) {
        const uint32_t st0 = sbase + s * STAGE_BYTES;
        const size_t kof = (size_t)c * 64 + sc * 8;
        #pragma unroll
        for (int it = 0; it < 8; it++) {
            const int row = it * 16 + srow;
            const int off = row * 128 + ((sc ^ (row & 7)) << 4);
            cp16(st0 + off,         A  + (size_t)(p0 + row) * KPAD + kof);
            cp16(st0 + 16384 + off, Bm + (size_t)(n0 + row) * KPAD + kof);
        }
        CP_COMMIT();
    };

    issue(0, 0);

    #pragma unroll 1
    for (int c = 0; c < NCH; c++) {
        if (c + 1 < NCH) {
            issue(c + 1, (c + 1) & 1);   // buf reuse safe: trailing barrier
            CP_WAIT(1);                   // chunk c arrived
        } else {
            CP_WAIT(0);
        }
        __syncthreads();

        const uint32_t sa = sbase + (c & 1) * STAGE_BYTES;
        const uint32_t sb = sa + 16384;

        #pragma unroll
        for (int ks = 0; ks < 4; ks++) {
            const int kch = ks * 2 + (lane >> 4);
            uint32_t af[4][4];
            #pragma unroll
            for (int mt = 0; mt < 4; mt++) {
                const int r = wm * 64 + mt * 16 + (lane & 15);
                ldsm4(af[mt][0], af[mt][1], af[mt][2], af[mt][3],
                      sa + r * 128 + ((kch ^ (r & 7)) << 4));
            }
            #pragma unroll
            for (int nt2 = 0; nt2 < 4; nt2++) {
                const int r = wn * 64 + nt2 * 16 + (lane & 15);
                uint32_t b0, b1, b2, b3;
                ldsm4(b0, b1, b2, b3, sb + r * 128 + ((kch ^ (r & 7)) << 4));
                #pragma unroll
                for (int mt = 0; mt < 4; mt++) {
                    mma16816h(acc[mt][2 * nt2],     af[mt][0], af[mt][1], af[mt][2], af[mt][3], b0, b2);
                    mma16816h(acc[mt][2 * nt2 + 1], af[mt][0], af[mt][1], af[mt][2], af[mt][3], b1, b3);
                }
            }
        }
        __syncthreads();   // all reads of this buffer done before next issue
    }

    __half* Ih = (__half*)g_Ih;
    #pragma unroll
    for (int mt = 0; mt < 4; mt++) {
        const int m = p0 + wm * 64 + mt * 16 + (lane >> 2);
        #pragma unroll
        for (int nt = 0; nt < 8; nt++) {
            const int n = n0 + wn * 64 + nt * 8 + (lane & 3) * 2;
            *reinterpret_cast<uint32_t*>(Ih + (size_t)m * NHID + n)       = acc[mt][nt][0];
            *reinterpret_cast<uint32_t*>(Ih + (size_t)(m + 8) * NHID + n) = acc[mt][nt][1];
        }
    }
}

// --------------------------------------------------------------------------
// k3: hidden LIF + fused output-layer neg contributions.
// cp.async double-buffered I staging (proven in R11).
// --------------------------------------------------------------------------
#define LCHUNK 40
#define LSTAGE (LCHUNK * 256 * 2)   // 20480 bytes

__global__ void __launch_bounds__(256) k_lif_hidden(const float* __restrict__ w2,
                                                    float* __restrict__ hs_out) {
    __shared__ __align__(16) uint8_t sbuf[2 * LSTAGE];
    const int tid = threadIdx.x;
    const int bh = blockIdx.x * 256 + tid;
    const int b = bh >> 10;
    const int h = bh & 1023;
    const int h0 = (blockIdx.x & 3) * 256;
    const uint32_t sb = smem_u32(sbuf);
    const __half* Ihg = (const __half*)g_Ih;
    float* obase = hs_out + (size_t)bh * TT;

    const int t8 = tid >> 5;
    const int sl = tid & 31;

    auto issue = [&](int chunk, int buf) {
        const uint32_t st0 = sb + buf * LSTAGE;
        #pragma unroll
        for (int q = 0; q < 5; q++) {
            const int t = t8 + 8 * q;
            const __half* src = Ihg + (size_t)(chunk * LCHUNK + t) * (BSZ * NHID)
                                + (size_t)b * NHID + h0 + sl * 8;
            cp16(st0 + t * 512 + sl * 16, src);
        }
        CP_COMMIT();
    };

    issue(0, 0);

    float v = 0.0f;
    #pragma unroll 1
    for (int c = 0; c < TT / LCHUNK; c++) {
        if (c + 1 < TT / LCHUNK) issue(c + 1, (c + 1) & 1);
        if (c + 1 < TT / LCHUNK) { CP_WAIT(1); } else { CP_WAIT(0); }
        __syncthreads();

        const __half* ssrc = (const __half*)(sbuf + (c & 1) * LSTAGE);
        const int tc = c * LCHUNK;
        float rr[LCHUNK];
        #pragma unroll
        for (int j = 0; j < LCHUNK; j++) {
            float I = __half2float(ssrc[j * 256 + tid]);
            v = __fadd_rn(__fadd_rn(v, __fmul_rn(ALPHA, -v)), I);
            float s;
            if (v >= 1.0f) { s = 1.0f; v = 0.0f; }
            else {
                s = 0.0f;
                float* pb = g_part + ((size_t)b * TT + (tc + j)) * NOUT;
                #pragma unroll
                for (int o = 0; o < NOUT; o++)
                    atomicAdd(pb + o, fmaxf(w2[(size_t)h * NOUT + o], 0.0f));
            }
            rr[j] = s;
        }
        #pragma unroll
        for (int q = 0; q < LCHUNK / 4; q++) {
            float4 o4 = make_float4(rr[4*q], rr[4*q+1], rr[4*q+2], rr[4*q+3]);
            *reinterpret_cast<float4*>(obase + tc + 4*q) = o4;
        }
        __syncthreads();
    }
}

// --------------------------------------------------------------------------
// k4b: output LIF + firing rates. thread per (b,o). colsum precomputed;
// t-loop in 10-wide chunks with batched neg loads.
// --------------------------------------------------------------------------
__global__ void k_out_lif(float* __restrict__ os_out,
                          float* __restrict__ fr_out) {
    const int gid = blockIdx.x * blockDim.x + threadIdx.x;
    if (gid >= BSZ * NOUT) return;
    const int b = gid / NOUT;
    const int o = gid - b * NOUT;

    const float colsum = g_colsum[o];
    const float* pb = g_part + (size_t)b * TT * NOUT + o;
    float v = 0.0f, cnt = 0.0f;
    float* ob = os_out + ((size_t)b * NOUT + o) * TT;

    #pragma unroll 1
    for (int tc = 0; tc < TT; tc += 10) {
        float neg[10];
        #pragma unroll
        for (int j = 0; j < 10; j++) {
            const int t = tc + j;
            neg[j] = (t > 0) ? pb[(size_t)(t - 1) * NOUT] : 0.0f;
        }
        float out[10];
        #pragma unroll
        for (int j = 0; j < 10; j++) {
            const int t = tc + j;
            float I = (t > 0) ? (colsum - neg[j]) : 0.0f;
            v = __fadd_rn(__fadd_rn(v, __fmul_rn(ALPHA, -v)), I);
            float s = (v >= 1.0f) ? 1.0f : 0.0f;
            if (v >= 1.0f) v = 0.0f;
            out[j] = s;
            cnt += s;
        }
        #pragma unroll
        for (int j = 0; j < 10; j++) ob[tc + j] = out[j];
    }
    fr_out[gid] = cnt / (float)TT;
}

// --------------------------------------------------------------------------
extern "C" void kernel_launch(void* const* d_in, const int* in_sizes, int n_in,
                              void* d_out, int out_size) {
    const float* sp = (const float*)d_in[0];   // (128, 784, 200)
    const float* w1 = (const float*)d_in[1];   // (784, 1024)
    const float* w2 = (const float*)d_in[2];   // (1024, 10)

    float* hs = (float*)d_out;                          // (B, NHID, T)
    float* os = hs + (size_t)BSZ * NHID * TT;           // (B, NOUT, T)
    float* fr = os + (size_t)BSZ * NOUT * TT;           // (B, NOUT)

    kA_stage<<<dim3(BSZ, 26), 256, 32 * 201 * sizeof(float)>>>(sp);
    kB_stage<<<dim3(32, 27), 256>>>(w1, w2);
    k_gemm<<<dim3(NHID / 128, NPAIR / 128), 128>>>();
    k_lif_hidden<<<(BSZ * NHID) / 256, 256>>>(w2, hs);
    k_out_lif<<<5, 256>>>(os, fr);
}